// round 14
// baseline (speedup 1.0000x reference)
#include <cuda_runtime.h>
#include <math_constants.h>
#include <cstdint>

// VQ-VAE vector quantizer, GB300 (PTX sm_103). Round 14: two lean kernels.
// A: DP4A screening (spill-free under the 128-reg/512-thread budget), masks
//    straight to a device-global array.
// B: exact fp32 refinement + ST epilogue + loss (also spill-free).
// inputs:  d_in[0] = inputs [64,64,32,32] fp32 NCHW, d_in[1] = emb_w [512,64] fp32
// output:  d_out fp32: loss[1] | out[4194304] NCHW | idx[65536]

#define DD        64
#define KK        512
#define NPIX      65536
#define BLOCK     512
#define GRID      128
#define OUT_ELEMS (NPIX * DD)

#define OFF_E    0                      // int8 codebook [512][64] = 32768 B
#define OFF_B    32768                  // [512] f32 ||e||^2
#define OFF_SCR  34816                  // 64 f32 scratch
#define SMEM_A   (OFF_SCR + 64 * 4)     // 35072 B (kernel A)

__device__ uint32_t g_masks[16 * NPIX]; // [w][n] candidate masks (4 MB)
__device__ float    g_part[GRID];
__device__ unsigned int g_cnt;          // zero-init; restored to 0 each run

// ================= Kernel A: screening =================
__global__ __launch_bounds__(BLOCK, 1)
void vq_screen(const float* __restrict__ in, const float* __restrict__ emb) {
    extern __shared__ char smem[];
    uint4* Ecb = (uint4*)(smem + OFF_E);
    float* sB  = (float*)(smem + OFF_B);
    float* scr = (float*)(smem + OFF_SCR);
    const int tid = threadIdx.x, wid = tid >> 5, lane = tid & 31;

    // codebook prologue: thread t owns code t
    const float* er = emb + tid * DD;
    float Bk = 0.0f, L1e = 0.0f, mxe = 0.0f;
    #pragma unroll 8
    for (int d = 0; d < DD; d++) {
        float v = er[d];
        Bk = __fadd_rn(Bk, __fmul_rn(v, v));    // exact R1/R2 order
        float a = fabsf(v);
        L1e += a;
        mxe = fmaxf(mxe, a);
    }
    sB[tid] = Bk;
    float m1 = mxe, m2 = L1e;
    #pragma unroll
    for (int o = 16; o > 0; o >>= 1) {
        m1 = fmaxf(m1, __shfl_xor_sync(~0u, m1, o));
        m2 = fmaxf(m2, __shfl_xor_sync(~0u, m2, o));
    }
    if (lane == 0) { scr[wid] = m1; scr[16 + wid] = m2; }
    __syncthreads();
    float maxe = scr[0], L1emax = scr[16];
    #pragma unroll
    for (int w = 1; w < 16; w++) {
        maxe   = fmaxf(maxe,   scr[w]);
        L1emax = fmaxf(L1emax, scr[16 + w]);
    }
    maxe = fmaxf(maxe, 1e-30f);
    const float se = maxe * (1.0f / 127.0f);
    const float inv_se = 127.0f / maxe;
    {
        uint32_t* Erow = (uint32_t*)(Ecb + tid * 4);
        #pragma unroll
        for (int i = 0; i < 16; i++) {
            int q0 = __float2int_rn(er[4 * i + 0] * inv_se);
            int q1 = __float2int_rn(er[4 * i + 1] * inv_se);
            int q2 = __float2int_rn(er[4 * i + 2] * inv_se);
            int q3 = __float2int_rn(er[4 * i + 3] * inv_se);
            Erow[i] = (uint32_t)(q0 & 0xFF) | ((uint32_t)(q1 & 0xFF) << 8) |
                      ((uint32_t)(q2 & 0xFF) << 16) | ((uint32_t)(q3 & 0xFF) << 24);
        }
    }
    __syncthreads();

    // pixel stats (A not needed here; only scales/margin inputs)
    const int n  = blockIdx.x * BLOCK + tid;
    const int b  = n >> 10;
    const int hw = n & 1023;
    const float* px = in + (size_t)b * 65536 + hw;

    float L1x = 0.f, mxx = 0.f;
    #pragma unroll
    for (int d = 0; d < DD; d += 4) {
        float v0 = px[(size_t)(d + 0) << 10];
        float v1 = px[(size_t)(d + 1) << 10];
        float v2 = px[(size_t)(d + 2) << 10];
        float v3 = px[(size_t)(d + 3) << 10];
        L1x += fabsf(v0) + fabsf(v1) + fabsf(v2) + fabsf(v3);
        mxx = fmaxf(mxx, fmaxf(fmaxf(fabsf(v0), fabsf(v1)),
                               fmaxf(fabsf(v2), fabsf(v3))));
    }
    mxx = fmaxf(mxx, 1e-30f);
    const float sx = mxx * (1.0f / 127.0f);
    const float inv_sx = 127.0f / mxx;

    uint32_t X[16];
    #pragma unroll
    for (int i = 0; i < 16; i++) {
        int q0 = __float2int_rn(px[(size_t)(4 * i + 0) << 10] * inv_sx);
        int q1 = __float2int_rn(px[(size_t)(4 * i + 1) << 10] * inv_sx);
        int q2 = __float2int_rn(px[(size_t)(4 * i + 2) << 10] * inv_sx);
        int q3 = __float2int_rn(px[(size_t)(4 * i + 3) << 10] * inv_sx);
        X[i] = (uint32_t)(q0 & 0xFF) | ((uint32_t)(q1 & 0xFF) << 8) |
               ((uint32_t)(q2 & 0xFF) << 16) | ((uint32_t)(q3 & 0xFF) << 24);
    }
    const float c2 = -2.0f * sx * se;
    const float margin = sx * L1emax + se * L1x + 16.0f * sx * se + 1e-6f; // 2*delta

    // DP4A screening; mask per 32-code chunk goes straight to global
    float thr = CUDART_INF_F;
    #pragma unroll 1
    for (int w = 0; w < 16; w++) {
        uint32_t m = 0;
        const uint4* ep = Ecb + (w * 32) * 4;
        const float* bp = sB + w * 32;
        #pragma unroll 2
        for (int j = 0; j < 32; j++) {
            uint4 qa = ep[4 * j + 0];
            uint4 qb = ep[4 * j + 1];
            int Pa = 0, Pb = 0;
            Pa = __dp4a((int)X[0],  (int)qa.x, Pa);
            Pa = __dp4a((int)X[1],  (int)qa.y, Pa);
            Pa = __dp4a((int)X[2],  (int)qa.z, Pa);
            Pa = __dp4a((int)X[3],  (int)qa.w, Pa);
            Pa = __dp4a((int)X[4],  (int)qb.x, Pa);
            Pa = __dp4a((int)X[5],  (int)qb.y, Pa);
            Pa = __dp4a((int)X[6],  (int)qb.z, Pa);
            Pa = __dp4a((int)X[7],  (int)qb.w, Pa);
            uint4 qc = ep[4 * j + 2];
            uint4 qd = ep[4 * j + 3];
            Pb = __dp4a((int)X[8],  (int)qc.x, Pb);
            Pb = __dp4a((int)X[9],  (int)qc.y, Pb);
            Pb = __dp4a((int)X[10], (int)qc.z, Pb);
            Pb = __dp4a((int)X[11], (int)qc.w, Pb);
            Pb = __dp4a((int)X[12], (int)qd.x, Pb);
            Pb = __dp4a((int)X[13], (int)qd.y, Pb);
            Pb = __dp4a((int)X[14], (int)qd.z, Pb);
            Pb = __dp4a((int)X[15], (int)qd.w, Pb);
            float s = fmaf(c2, (float)(Pa + Pb), bp[j]);
            m = (m >> 1) | ((s <= thr) ? 0x80000000u : 0u);
            thr = fminf(thr, __fadd_rn(s, margin));
        }
        g_masks[w * NPIX + n] = m;      // coalesced STG.32
    }
}

// ================= Kernel B: refinement + epilogue + loss =================
__global__ __launch_bounds__(BLOCK, 1)
void vq_refine(const float* __restrict__ in, const float* __restrict__ emb,
               float* __restrict__ out) {
    __shared__ float sB[KK];
    __shared__ float scr[16];
    const int tid = threadIdx.x, wid = tid >> 5, lane = tid & 31;

    // ||e||^2 prologue (exact order, identical values to kernel A)
    {
        const float* er = emb + tid * DD;
        float Bk = 0.0f;
        #pragma unroll 8
        for (int d = 0; d < DD; d++) {
            float v = er[d];
            Bk = __fadd_rn(Bk, __fmul_rn(v, v));
        }
        sB[tid] = Bk;
    }
    __syncthreads();

    const int n  = blockIdx.x * BLOCK + tid;
    const int b  = n >> 10;
    const int hw = n & 1023;
    const float* px = in + (size_t)b * 65536 + hw;

    // A in the proven R1 order (bit-identical recompute)
    float a0 = 0.f, a1 = 0.f, a2 = 0.f, a3 = 0.f;
    #pragma unroll
    for (int d = 0; d < DD; d += 4) {
        float v0 = px[(size_t)(d + 0) << 10];
        float v1 = px[(size_t)(d + 1) << 10];
        float v2 = px[(size_t)(d + 2) << 10];
        float v3 = px[(size_t)(d + 3) << 10];
        a0 = __fadd_rn(a0, __fmul_rn(v0, v0));
        a1 = __fadd_rn(a1, __fmul_rn(v1, v1));
        a2 = __fadd_rn(a2, __fmul_rn(v2, v2));
        a3 = __fadd_rn(a3, __fmul_rn(v3, v3));
    }
    const float A = __fadd_rn(__fadd_rn(a0, a2), __fadd_rn(a1, a3));

    // exact refinement (bit-matches R2): ascending k, strict '<'
    float best = CUDART_INF_F;
    int bi = 0;
    #pragma unroll 1
    for (int w = 0; w < 16; w++) {
        uint32_t m = g_masks[w * NPIX + n];   // coalesced LDG.32
        while (m) {
            int j = __ffs(m) - 1;
            m &= m - 1;
            int kk = w * 32 + j;
            const float4* e4p = (const float4*)(emb + kk * DD);
            float p = 0.0f;
            #pragma unroll
            for (int q = 0; q < DD / 4; q++) {
                float4 e4 = e4p[q];
                p = fmaf(e4.x, px[(size_t)(4 * q + 0) << 10], p);
                p = fmaf(e4.y, px[(size_t)(4 * q + 1) << 10], p);
                p = fmaf(e4.z, px[(size_t)(4 * q + 2) << 10], p);
                p = fmaf(e4.w, px[(size_t)(4 * q + 3) << 10], p);
            }
            float dist = __fsub_rn(__fadd_rn(A, sB[kk]), __fmul_rn(2.0f, p));
            if (dist < best) { best = dist; bi = kk; }
        }
    }

    // epilogue (bit-matches R2)
    float* pout = out + 1 + (size_t)b * 65536 + hw;
    const float* qr = emb + bi * DD;
    float sq = 0.0f;
    #pragma unroll 8
    for (int d = 0; d < DD; d++) {
        float xd   = px[(size_t)d << 10];
        float qd   = qr[d];
        float diff = __fsub_rn(qd, xd);
        sq = fmaf(diff, diff, sq);
        pout[(size_t)d << 10] = __fadd_rn(xd, diff);
    }
    out[1 + (size_t)OUT_ELEMS + n] = (float)bi;

    // loss: block reduce -> per-CTA partial; last CTA finalizes
    #pragma unroll
    for (int o = 16; o > 0; o >>= 1)
        sq += __shfl_down_sync(~0u, sq, o);
    if (lane == 0) scr[wid] = sq;
    __syncthreads();
    if (tid == 0) {
        float s = 0.0f;
        #pragma unroll
        for (int w = 0; w < 16; w++) s += scr[w];
        g_part[blockIdx.x] = s;
        __threadfence();
        unsigned int prev = atomicAdd(&g_cnt, 1u);
        if (prev == GRID - 1) {
            float tot = 0.0f;
            volatile float* gp = g_part;
            #pragma unroll
            for (int i = 0; i < GRID; i++) tot += gp[i];
            float mmean = tot * (1.0f / (float)OUT_ELEMS);
            out[0] = __fadd_rn(mmean, __fmul_rn(0.25f, mmean));
            g_cnt = 0u;
        }
    }
}

extern "C" void kernel_launch(void* const* d_in, const int* in_sizes, int n_in,
                              void* d_out, int out_size) {
    (void)in_sizes; (void)n_in; (void)out_size;
    const float* in  = (const float*)d_in[0];
    const float* emb = (const float*)d_in[1];
    float* out = (float*)d_out;

    cudaFuncSetAttribute(vq_screen, cudaFuncAttributeMaxDynamicSharedMemorySize,
                         SMEM_A);
    vq_screen<<<GRID, BLOCK, SMEM_A>>>(in, emb);
    vq_refine<<<GRID, BLOCK>>>(in, emb, out);
}

// round 15
// speedup vs baseline: 1.1288x; 1.1288x over previous
#include <cuda_runtime.h>
#include <math_constants.h>
#include <cstdint>

// VQ-VAE vector quantizer, GB300 (PTX sm_103). Round 15: DP4A screening with
// codebook reads via warp-uniform __ldg (coalescer dedups to 1 sector/instr,
// bypassing the smem-crossbar byte duplication that bound R6-R14) + exact
// fp32 refinement. Graph: prep kernel -> main kernel.
// inputs:  d_in[0] = inputs [64,64,32,32] fp32 NCHW, d_in[1] = emb_w [512,64] fp32
// output:  d_out fp32: loss[1] | out[4194304] NCHW | idx[65536]

#define DD        64
#define KK        512
#define NPIX      65536
#define BLOCK     512
#define GRID      128
#define OUT_ELEMS (NPIX * DD)

#define OFF_SCR  0                       // 64 f32 scratch
#define OFF_MSK  256                     // [512][17] u32 candidate masks
#define SMEM_TOTAL (OFF_MSK + BLOCK * 17 * 4)   // 35072 B

__device__ uint4  g_E[KK * 4];          // int8-packed codebook rows (32 KB)
__device__ float  g_B[KK];              // ||e_k||^2 (exact R1/R2 order)
__device__ float  g_sc[2];              // {se, L1emax}
__device__ float  g_part[GRID];
__device__ unsigned int g_cnt;          // zero-init; restored to 0 each run

// ---- prep: quantize codebook into globals (1 CTA, 512 threads) ----
__global__ __launch_bounds__(BLOCK, 1)
void vq_prep(const float* __restrict__ emb) {
    __shared__ float red[32];
    const int tid = threadIdx.x, wid = tid >> 5, lane = tid & 31;
    const float* er = emb + tid * DD;

    float Bk = 0.0f, L1e = 0.0f, mxe = 0.0f;
    #pragma unroll 8
    for (int d = 0; d < DD; d++) {
        float v = er[d];
        Bk = __fadd_rn(Bk, __fmul_rn(v, v));   // R1/R2-proven exact order
        float a = fabsf(v);
        L1e += a;
        mxe = fmaxf(mxe, a);
    }
    g_B[tid] = Bk;

    float m1 = mxe, m2 = L1e;
    #pragma unroll
    for (int o = 16; o > 0; o >>= 1) {
        m1 = fmaxf(m1, __shfl_xor_sync(~0u, m1, o));
        m2 = fmaxf(m2, __shfl_xor_sync(~0u, m2, o));
    }
    if (lane == 0) { red[wid] = m1; red[16 + wid] = m2; }
    __syncthreads();
    float maxe = red[0], L1emax = red[16];
    #pragma unroll
    for (int w = 1; w < 16; w++) {
        maxe   = fmaxf(maxe,   red[w]);
        L1emax = fmaxf(L1emax, red[16 + w]);
    }
    maxe = fmaxf(maxe, 1e-30f);
    const float inv_se = 127.0f / maxe;

    uint32_t* Erow = (uint32_t*)&g_E[tid * 4];
    #pragma unroll
    for (int i = 0; i < 16; i++) {
        int q0 = __float2int_rn(er[4 * i + 0] * inv_se);
        int q1 = __float2int_rn(er[4 * i + 1] * inv_se);
        int q2 = __float2int_rn(er[4 * i + 2] * inv_se);
        int q3 = __float2int_rn(er[4 * i + 3] * inv_se);
        Erow[i] = (uint32_t)(q0 & 0xFF) | ((uint32_t)(q1 & 0xFF) << 8) |
                  ((uint32_t)(q2 & 0xFF) << 16) | ((uint32_t)(q3 & 0xFF) << 24);
    }
    if (tid == 0) {
        g_sc[0] = maxe * (1.0f / 127.0f);   // se
        g_sc[1] = L1emax;
    }
}

// ---- main ----
__global__ __launch_bounds__(BLOCK, 1)
void vq_main(const float* __restrict__ in, const float* __restrict__ emb,
             float* __restrict__ out) {
    extern __shared__ char smem[];
    float*    scr = (float*)(smem + OFF_SCR);
    uint32_t* msk = (uint32_t*)(smem + OFF_MSK);
    const int tid = threadIdx.x, wid = tid >> 5, lane = tid & 31;

    const float se     = __ldg(&g_sc[0]);
    const float L1emax = __ldg(&g_sc[1]);

    // ---- pixel stats (L1, max for scales/margin) ----
    const int n  = blockIdx.x * BLOCK + tid;
    const int b  = n >> 10;
    const int hw = n & 1023;
    const float* px = in + (size_t)b * 65536 + hw;

    float L1x = 0.f, mxx = 0.f;
    #pragma unroll
    for (int d = 0; d < DD; d += 4) {
        float v0 = px[(size_t)(d + 0) << 10];
        float v1 = px[(size_t)(d + 1) << 10];
        float v2 = px[(size_t)(d + 2) << 10];
        float v3 = px[(size_t)(d + 3) << 10];
        L1x += fabsf(v0) + fabsf(v1) + fabsf(v2) + fabsf(v3);
        mxx = fmaxf(mxx, fmaxf(fmaxf(fabsf(v0), fabsf(v1)),
                               fmaxf(fabsf(v2), fabsf(v3))));
    }
    mxx = fmaxf(mxx, 1e-30f);
    const float sx = mxx * (1.0f / 127.0f);
    const float inv_sx = 127.0f / mxx;

    uint32_t X[16];
    #pragma unroll
    for (int i = 0; i < 16; i++) {
        int q0 = __float2int_rn(px[(size_t)(4 * i + 0) << 10] * inv_sx);
        int q1 = __float2int_rn(px[(size_t)(4 * i + 1) << 10] * inv_sx);
        int q2 = __float2int_rn(px[(size_t)(4 * i + 2) << 10] * inv_sx);
        int q3 = __float2int_rn(px[(size_t)(4 * i + 3) << 10] * inv_sx);
        X[i] = (uint32_t)(q0 & 0xFF) | ((uint32_t)(q1 & 0xFF) << 8) |
               ((uint32_t)(q2 & 0xFF) << 16) | ((uint32_t)(q3 & 0xFF) << 24);
    }
    const float c2 = -2.0f * sx * se;
    const float margin = sx * L1emax + se * L1x + 16.0f * sx * se + 1e-6f; // 2*delta

    // ---- DP4A screening: codebook via warp-uniform __ldg (sector-deduped) ----
    float thr = CUDART_INF_F;
    uint32_t* mrow = msk + tid * 17;
    #pragma unroll 1
    for (int w = 0; w < 16; w++) {
        uint32_t m = 0;
        const uint4* ep = g_E + (w * 32) * 4;
        const float* bp = g_B + w * 32;
        #pragma unroll 2
        for (int j = 0; j < 32; j++) {
            uint4 qa = __ldg(ep + 4 * j + 0);
            uint4 qb = __ldg(ep + 4 * j + 1);
            int Pa = 0, Pb = 0;
            Pa = __dp4a((int)X[0],  (int)qa.x, Pa);
            Pa = __dp4a((int)X[1],  (int)qa.y, Pa);
            Pa = __dp4a((int)X[2],  (int)qa.z, Pa);
            Pa = __dp4a((int)X[3],  (int)qa.w, Pa);
            Pa = __dp4a((int)X[4],  (int)qb.x, Pa);
            Pa = __dp4a((int)X[5],  (int)qb.y, Pa);
            Pa = __dp4a((int)X[6],  (int)qb.z, Pa);
            Pa = __dp4a((int)X[7],  (int)qb.w, Pa);
            uint4 qc = __ldg(ep + 4 * j + 2);
            uint4 qd = __ldg(ep + 4 * j + 3);
            Pb = __dp4a((int)X[8],  (int)qc.x, Pb);
            Pb = __dp4a((int)X[9],  (int)qc.y, Pb);
            Pb = __dp4a((int)X[10], (int)qc.z, Pb);
            Pb = __dp4a((int)X[11], (int)qc.w, Pb);
            Pb = __dp4a((int)X[12], (int)qd.x, Pb);
            Pb = __dp4a((int)X[13], (int)qd.y, Pb);
            Pb = __dp4a((int)X[14], (int)qd.z, Pb);
            Pb = __dp4a((int)X[15], (int)qd.w, Pb);
            float s = fmaf(c2, (float)(Pa + Pb), __ldg(bp + j));
            m = (m >> 1) | ((s <= thr) ? 0x80000000u : 0u);  // bit j after 32
            thr = fminf(thr, __fadd_rn(s, margin));
        }
        mrow[w] = m;
    }

    // ---- exact refinement (bit-matches R2): ascending k, strict '<';
    //      x reloaded from L1-hot global, modest unroll (reg pressure) ----
    float a0 = 0.f, a1 = 0.f, a2 = 0.f, a3 = 0.f;
    #pragma unroll
    for (int d = 0; d < DD; d += 4) {
        float v0 = px[(size_t)(d + 0) << 10];
        float v1 = px[(size_t)(d + 1) << 10];
        float v2 = px[(size_t)(d + 2) << 10];
        float v3 = px[(size_t)(d + 3) << 10];
        a0 = __fadd_rn(a0, __fmul_rn(v0, v0));
        a1 = __fadd_rn(a1, __fmul_rn(v1, v1));
        a2 = __fadd_rn(a2, __fmul_rn(v2, v2));
        a3 = __fadd_rn(a3, __fmul_rn(v3, v3));
    }
    const float A = __fadd_rn(__fadd_rn(a0, a2), __fadd_rn(a1, a3));

    float best = CUDART_INF_F;
    int bi = 0;
    #pragma unroll 1
    for (int w = 0; w < 16; w++) {
        uint32_t m = mrow[w];
        while (m) {
            int j = __ffs(m) - 1;
            m &= m - 1;
            int kk = w * 32 + j;
            const float4* e4p = (const float4*)(emb + kk * DD);
            float p = 0.0f;
            #pragma unroll 4
            for (int q = 0; q < DD / 4; q++) {
                float4 e4 = e4p[q];
                p = fmaf(e4.x, px[(size_t)(4 * q + 0) << 10], p);
                p = fmaf(e4.y, px[(size_t)(4 * q + 1) << 10], p);
                p = fmaf(e4.z, px[(size_t)(4 * q + 2) << 10], p);
                p = fmaf(e4.w, px[(size_t)(4 * q + 3) << 10], p);
            }
            float dist = __fsub_rn(__fadd_rn(A, __ldg(&g_B[kk])), __fmul_rn(2.0f, p));
            if (dist < best) { best = dist; bi = kk; }
        }
    }

    // ---- epilogue (bit-matches R2): stream x from global ----
    float* pout = out + 1 + (size_t)b * 65536 + hw;
    const float* qr = emb + bi * DD;
    float sq = 0.0f;
    #pragma unroll 8
    for (int d = 0; d < DD; d++) {
        float xd   = px[(size_t)d << 10];
        float qd   = qr[d];
        float diff = __fsub_rn(qd, xd);
        sq = fmaf(diff, diff, sq);
        pout[(size_t)d << 10] = __fadd_rn(xd, diff);
    }
    out[1 + (size_t)OUT_ELEMS + n] = (float)bi;

    // ---- loss: block reduce -> per-CTA partial; last CTA finalizes ----
    #pragma unroll
    for (int o = 16; o > 0; o >>= 1)
        sq += __shfl_down_sync(~0u, sq, o);
    if (lane == 0) scr[wid] = sq;
    __syncthreads();
    if (tid == 0) {
        float s = 0.0f;
        #pragma unroll
        for (int w = 0; w < 16; w++) s += scr[w];
        g_part[blockIdx.x] = s;
        __threadfence();
        unsigned int prev = atomicAdd(&g_cnt, 1u);
        if (prev == GRID - 1) {
            float tot = 0.0f;
            volatile float* gp = g_part;
            #pragma unroll
            for (int i = 0; i < GRID; i++) tot += gp[i];
            float mmean = tot * (1.0f / (float)OUT_ELEMS);
            out[0] = __fadd_rn(mmean, __fmul_rn(0.25f, mmean));
            g_cnt = 0u;
        }
    }
}

extern "C" void kernel_launch(void* const* d_in, const int* in_sizes, int n_in,
                              void* d_out, int out_size) {
    (void)in_sizes; (void)n_in; (void)out_size;
    const float* in  = (const float*)d_in[0];
    const float* emb = (const float*)d_in[1];
    float* out = (float*)d_out;

    cudaFuncSetAttribute(vq_main, cudaFuncAttributeMaxDynamicSharedMemorySize,
                         SMEM_TOTAL);
    vq_prep<<<1, BLOCK>>>(emb);
    vq_main<<<GRID, BLOCK, SMEM_TOTAL>>>(in, emb, out);
}

// round 16
// speedup vs baseline: 1.3015x; 1.1530x over previous
#include <cuda_runtime.h>
#include <math_constants.h>
#include <cstdint>

// VQ-VAE vector quantizer, GB300 (PTX sm_103). Round 16: DP4A screening with
// codebook rows distributed via the warp SHUFFLE network (4 conflict-free
// LDS.128 per 32-code chunk) instead of per-code broadcast LDS — removes the
// crossbar byte-replication wall of R6-R15. Exact fp32 refinement unchanged.
// inputs:  d_in[0] = inputs [64,64,32,32] fp32 NCHW, d_in[1] = emb_w [512,64] fp32
// output:  d_out fp32: loss[1] | out[4194304] NCHW | idx[65536]

#define DD        64
#define KK        512
#define NPIX      65536
#define BLOCK     512
#define GRID      128
#define OUT_ELEMS (NPIX * DD)

#define OFF_E    0                      // int8 codebook [512][64] = 32768 B
#define OFF_B    32768                  // [512] f32 ||e||^2
#define OFF_SCR  34816                  // 64 f32 scratch
#define OFF_MSK  35072                  // [512][17] u32 candidate masks
#define SMEM_TOTAL (OFF_MSK + BLOCK * 17 * 4)   // 69888 B

__device__ float g_part[GRID];
__device__ unsigned int g_cnt;          // zero-init; restored to 0 each run

__global__ __launch_bounds__(BLOCK, 1)
void vq_main(const float* __restrict__ in, const float* __restrict__ emb,
             float* __restrict__ out) {
    extern __shared__ char smem[];
    uint4* Ecb = (uint4*)(smem + OFF_E);
    float* sB  = (float*)(smem + OFF_B);
    float* scr = (float*)(smem + OFF_SCR);
    uint32_t* msk = (uint32_t*)(smem + OFF_MSK);
    const int tid = threadIdx.x, wid = tid >> 5, lane = tid & 31;

    // ---- codebook prologue: thread t owns code t (BLOCK == KK) ----
    const float* er = emb + tid * DD;
    float Bk = 0.0f, L1e = 0.0f, mxe = 0.0f;
    #pragma unroll 8
    for (int d = 0; d < DD; d++) {
        float v = er[d];
        Bk = __fadd_rn(Bk, __fmul_rn(v, v));    // R1/R2-proven exact order
        float a = fabsf(v);
        L1e += a;
        mxe = fmaxf(mxe, a);
    }
    sB[tid] = Bk;
    float m1 = mxe, m2 = L1e;
    #pragma unroll
    for (int o = 16; o > 0; o >>= 1) {
        m1 = fmaxf(m1, __shfl_xor_sync(~0u, m1, o));
        m2 = fmaxf(m2, __shfl_xor_sync(~0u, m2, o));
    }
    if (lane == 0) { scr[wid] = m1; scr[16 + wid] = m2; }
    __syncthreads();
    float maxe = scr[0], L1emax = scr[16];
    #pragma unroll
    for (int w = 1; w < 16; w++) {
        maxe   = fmaxf(maxe,   scr[w]);
        L1emax = fmaxf(L1emax, scr[16 + w]);
    }
    maxe = fmaxf(maxe, 1e-30f);
    const float se = maxe * (1.0f / 127.0f);
    const float inv_se = 127.0f / maxe;
    {   // quantize + pack own code row: [64] int8 -> 16 u32
        uint32_t* Erow = (uint32_t*)(Ecb + tid * 4);
        #pragma unroll
        for (int i = 0; i < 16; i++) {
            int q0 = __float2int_rn(er[4 * i + 0] * inv_se);
            int q1 = __float2int_rn(er[4 * i + 1] * inv_se);
            int q2 = __float2int_rn(er[4 * i + 2] * inv_se);
            int q3 = __float2int_rn(er[4 * i + 3] * inv_se);
            Erow[i] = (uint32_t)(q0 & 0xFF) | ((uint32_t)(q1 & 0xFF) << 8) |
                      ((uint32_t)(q2 & 0xFF) << 16) | ((uint32_t)(q3 & 0xFF) << 24);
        }
    }
    __syncthreads();

    // ---- pixel stats (L1, max) ----
    const int n  = blockIdx.x * BLOCK + tid;
    const int b  = n >> 10;
    const int hw = n & 1023;
    const float* px = in + (size_t)b * 65536 + hw;

    float L1x = 0.f, mxx = 0.f;
    #pragma unroll
    for (int d = 0; d < DD; d += 4) {
        float v0 = px[(size_t)(d + 0) << 10];
        float v1 = px[(size_t)(d + 1) << 10];
        float v2 = px[(size_t)(d + 2) << 10];
        float v3 = px[(size_t)(d + 3) << 10];
        L1x += fabsf(v0) + fabsf(v1) + fabsf(v2) + fabsf(v3);
        mxx = fmaxf(mxx, fmaxf(fmaxf(fabsf(v0), fabsf(v1)),
                               fmaxf(fabsf(v2), fabsf(v3))));
    }
    mxx = fmaxf(mxx, 1e-30f);
    const float sx = mxx * (1.0f / 127.0f);
    const float inv_sx = 127.0f / mxx;

    uint32_t X[16];
    #pragma unroll
    for (int i = 0; i < 16; i++) {
        int q0 = __float2int_rn(px[(size_t)(4 * i + 0) << 10] * inv_sx);
        int q1 = __float2int_rn(px[(size_t)(4 * i + 1) << 10] * inv_sx);
        int q2 = __float2int_rn(px[(size_t)(4 * i + 2) << 10] * inv_sx);
        int q3 = __float2int_rn(px[(size_t)(4 * i + 3) << 10] * inv_sx);
        X[i] = (uint32_t)(q0 & 0xFF) | ((uint32_t)(q1 & 0xFF) << 8) |
               ((uint32_t)(q2 & 0xFF) << 16) | ((uint32_t)(q3 & 0xFF) << 24);
    }
    const float c2 = -2.0f * sx * se;
    const float margin = sx * L1emax + se * L1x + 16.0f * sx * se + 1e-6f; // 2*delta

    // ---- DP4A screening: code rows via shuffle, crossbar nearly idle ----
    float thr = CUDART_INF_F;
    uint32_t* mrow = msk + tid * 17;
    #pragma unroll 1
    for (int w = 0; w < 16; w++) {
        // cooperative load: this lane holds code (w*32+lane)'s packed row
        int cw[16];
        {
            const uint4* ep = Ecb + (w * 32 + lane) * 4;   // distinct rows
            uint4 qa = ep[0], qb = ep[1], qc = ep[2], qd = ep[3];
            cw[0]  = (int)qa.x; cw[1]  = (int)qa.y; cw[2]  = (int)qa.z; cw[3]  = (int)qa.w;
            cw[4]  = (int)qb.x; cw[5]  = (int)qb.y; cw[6]  = (int)qb.z; cw[7]  = (int)qb.w;
            cw[8]  = (int)qc.x; cw[9]  = (int)qc.y; cw[10] = (int)qc.z; cw[11] = (int)qc.w;
            cw[12] = (int)qd.x; cw[13] = (int)qd.y; cw[14] = (int)qd.z; cw[15] = (int)qd.w;
        }
        const float* bp = sB + w * 32;
        uint32_t m = 0;
        #pragma unroll 2
        for (int j = 0; j < 32; j++) {
            int Pa = 0, Pb = 0;
            Pa = __dp4a((int)X[0],  __shfl_sync(~0u, cw[0],  j), Pa);
            Pb = __dp4a((int)X[8],  __shfl_sync(~0u, cw[8],  j), Pb);
            Pa = __dp4a((int)X[1],  __shfl_sync(~0u, cw[1],  j), Pa);
            Pb = __dp4a((int)X[9],  __shfl_sync(~0u, cw[9],  j), Pb);
            Pa = __dp4a((int)X[2],  __shfl_sync(~0u, cw[2],  j), Pa);
            Pb = __dp4a((int)X[10], __shfl_sync(~0u, cw[10], j), Pb);
            Pa = __dp4a((int)X[3],  __shfl_sync(~0u, cw[3],  j), Pa);
            Pb = __dp4a((int)X[11], __shfl_sync(~0u, cw[11], j), Pb);
            Pa = __dp4a((int)X[4],  __shfl_sync(~0u, cw[4],  j), Pa);
            Pb = __dp4a((int)X[12], __shfl_sync(~0u, cw[12], j), Pb);
            Pa = __dp4a((int)X[5],  __shfl_sync(~0u, cw[5],  j), Pa);
            Pb = __dp4a((int)X[13], __shfl_sync(~0u, cw[13], j), Pb);
            Pa = __dp4a((int)X[6],  __shfl_sync(~0u, cw[6],  j), Pa);
            Pb = __dp4a((int)X[14], __shfl_sync(~0u, cw[14], j), Pb);
            Pa = __dp4a((int)X[7],  __shfl_sync(~0u, cw[7],  j), Pa);
            Pb = __dp4a((int)X[15], __shfl_sync(~0u, cw[15], j), Pb);
            float s = fmaf(c2, (float)(Pa + Pb), bp[j]);   // bp: 1-cyc broadcast
            m = (m >> 1) | ((s <= thr) ? 0x80000000u : 0u);  // bit j after 32
            thr = fminf(thr, __fadd_rn(s, margin));
        }
        mrow[w] = m;
    }

    // ---- exact refinement (bit-matches R2): ascending k, strict '<' ----
    float a0 = 0.f, a1 = 0.f, a2 = 0.f, a3 = 0.f;
    #pragma unroll
    for (int d = 0; d < DD; d += 4) {
        float v0 = px[(size_t)(d + 0) << 10];
        float v1 = px[(size_t)(d + 1) << 10];
        float v2 = px[(size_t)(d + 2) << 10];
        float v3 = px[(size_t)(d + 3) << 10];
        a0 = __fadd_rn(a0, __fmul_rn(v0, v0));
        a1 = __fadd_rn(a1, __fmul_rn(v1, v1));
        a2 = __fadd_rn(a2, __fmul_rn(v2, v2));
        a3 = __fadd_rn(a3, __fmul_rn(v3, v3));
    }
    const float A = __fadd_rn(__fadd_rn(a0, a2), __fadd_rn(a1, a3));

    float best = CUDART_INF_F;
    int bi = 0;
    #pragma unroll 1
    for (int w = 0; w < 16; w++) {
        uint32_t m = mrow[w];
        while (m) {
            int j = __ffs(m) - 1;
            m &= m - 1;
            int kk = w * 32 + j;
            const float4* e4p = (const float4*)(emb + kk * DD);
            float p = 0.0f;
            #pragma unroll 4
            for (int q = 0; q < DD / 4; q++) {
                float4 e4 = e4p[q];
                p = fmaf(e4.x, px[(size_t)(4 * q + 0) << 10], p);
                p = fmaf(e4.y, px[(size_t)(4 * q + 1) << 10], p);
                p = fmaf(e4.z, px[(size_t)(4 * q + 2) << 10], p);
                p = fmaf(e4.w, px[(size_t)(4 * q + 3) << 10], p);
            }
            float dist = __fsub_rn(__fadd_rn(A, sB[kk]), __fmul_rn(2.0f, p));
            if (dist < best) { best = dist; bi = kk; }
        }
    }

    // ---- epilogue (bit-matches R2): stream x from global ----
    float* pout = out + 1 + (size_t)b * 65536 + hw;
    const float* qr = emb + bi * DD;
    float sq = 0.0f;
    #pragma unroll 8
    for (int d = 0; d < DD; d++) {
        float xd   = px[(size_t)d << 10];
        float qd   = qr[d];
        float diff = __fsub_rn(qd, xd);
        sq = fmaf(diff, diff, sq);
        pout[(size_t)d << 10] = __fadd_rn(xd, diff);
    }
    out[1 + (size_t)OUT_ELEMS + n] = (float)bi;

    // ---- loss: block reduce -> per-CTA partial; last CTA finalizes ----
    __syncthreads();
    #pragma unroll
    for (int o = 16; o > 0; o >>= 1)
        sq += __shfl_down_sync(~0u, sq, o);
    if (lane == 0) scr[wid] = sq;
    __syncthreads();
    if (tid == 0) {
        float s = 0.0f;
        #pragma unroll
        for (int w = 0; w < 16; w++) s += scr[w];
        g_part[blockIdx.x] = s;
        __threadfence();
        unsigned int prev = atomicAdd(&g_cnt, 1u);
        if (prev == GRID - 1) {
            float tot = 0.0f;
            volatile float* gp = g_part;
            #pragma unroll
            for (int i = 0; i < GRID; i++) tot += gp[i];
            float mmean = tot * (1.0f / (float)OUT_ELEMS);
            out[0] = __fadd_rn(mmean, __fmul_rn(0.25f, mmean));
            g_cnt = 0u;
        }
    }
}

extern "C" void kernel_launch(void* const* d_in, const int* in_sizes, int n_in,
                              void* d_out, int out_size) {
    (void)in_sizes; (void)n_in; (void)out_size;
    cudaFuncSetAttribute(vq_main, cudaFuncAttributeMaxDynamicSharedMemorySize,
                         SMEM_TOTAL);
    vq_main<<<GRID, BLOCK, SMEM_TOTAL>>>((const float*)d_in[0],
                                         (const float*)d_in[1], (float*)d_out);
}